// round 8
// baseline (speedup 1.0000x reference)
#include <cuda_runtime.h>
#include <cstdint>
#include <cstring>
#include <math.h>

// ---------------------------------------------------------------------------
// DataAugmenter: zoom(linear/nearest) -> flips -> gaussian noise -> gamma.
// JAX threefry2x32, threefry_partitionable=True (validated R2).
// R8: fork-join overlap (R7) + gamma recompute (R4, bit-identical) so the
//     gamma sample's out_img is written exactly once. Recompute cost hides
//     under the concurrent aug(rest); removes ~12-16 MB of DRAM traffic.
// ---------------------------------------------------------------------------

static const int BATCH = 8;
static const int NSIDE = 128;
static const int NVOX  = NSIDE * NSIDE * NSIDE;   // 2^21 per sample
static const int NV4   = NVOX / 4;                // float4 per sample

#define F32_INF __int_as_float(0x7F800000)

// ----------------------------- threefry2x32 --------------------------------
__host__ __device__ inline uint32_t rotl32(uint32_t v, int d) {
    return (v << d) | (v >> (32 - d));
}

__host__ __device__ inline void tf2x32(uint32_t k0, uint32_t k1,
                                       uint32_t c0, uint32_t c1,
                                       uint32_t& o0, uint32_t& o1) {
    uint32_t ks0 = k0, ks1 = k1, ks2 = 0x1BD11BDAu ^ k0 ^ k1;
    uint32_t x0 = c0 + ks0, x1 = c1 + ks1;
#define TFR(r) { x0 += x1; x1 = rotl32(x1, r); x1 ^= x0; }
    TFR(13) TFR(15) TFR(26) TFR(6)
    x0 += ks1; x1 += ks2 + 1u;
    TFR(17) TFR(29) TFR(16) TFR(24)
    x0 += ks2; x1 += ks0 + 2u;
    TFR(13) TFR(15) TFR(26) TFR(6)
    x0 += ks0; x1 += ks1 + 3u;
    TFR(17) TFR(29) TFR(16) TFR(24)
    x0 += ks1; x1 += ks2 + 4u;
    TFR(13) TFR(15) TFR(26) TFR(6)
    x0 += ks2; x1 += ks0 + 5u;
#undef TFR
    o0 = x0; o1 = x1;
}

__host__ __device__ inline float bits_to_unit(uint32_t bits) {
    uint32_t fb = (bits >> 9) | 0x3F800000u;
    float f;
#ifdef __CUDA_ARCH__
    f = __uint_as_float(fb);
#else
    memcpy(&f, &fb, 4);
#endif
    return f - 1.0f;
}

// XLA f32 ErfInv (Giles polynomial)
__device__ inline float erfinv_xla(float x) {
    float w = -log1pf(-x * x);
    float p;
    if (w < 5.0f) {
        w = w - 2.5f;
        p = 2.81022636e-08f;
        p = fmaf(p, w, 3.43273939e-07f);
        p = fmaf(p, w, -3.5233877e-06f);
        p = fmaf(p, w, -4.39150654e-06f);
        p = fmaf(p, w, 0.00021858087f);
        p = fmaf(p, w, -0.00125372503f);
        p = fmaf(p, w, -0.00417768164f);
        p = fmaf(p, w, 0.246640727f);
        p = fmaf(p, w, 1.50140941f);
    } else {
        w = sqrtf(w) - 3.0f;
        p = -0.000200214257f;
        p = fmaf(p, w, 0.000100950558f);
        p = fmaf(p, w, 0.00134934322f);
        p = fmaf(p, w, -0.00367342844f);
        p = fmaf(p, w, 0.00573950773f);
        p = fmaf(p, w, -0.0076224613f);
        p = fmaf(p, w, 0.00943887047f);
        p = fmaf(p, w, 1.00167406f);
        p = fmaf(p, w, 2.83297682f);
    }
    return p * x;
}

// ----------------------- ordered-uint min/max encoding ----------------------
__device__ inline unsigned encf(float f) {
    unsigned u = __float_as_uint(f);
    return (u & 0x80000000u) ? ~u : (u | 0x80000000u);
}
__device__ inline float decf(unsigned e) {
    unsigned u = (e & 0x80000000u) ? (e ^ 0x80000000u) : ~e;
    return __uint_as_float(u);
}

// Stats via atomicMax with identity 0 (zero-init compatible):
// max as encf(v), min as ~encf(v).
__device__ unsigned g_maxenc[BATCH];
__device__ unsigned g_negmin[BATCH];
__device__ unsigned g_done;

// ------------------------------- params ------------------------------------
struct SampleParams {
    float z;
    float stdv;
    int b;            // actual sample index
    int fh, fw, fd;
    int need_stats;   // gamma sample: do stats, skip out_img store
    uint32_t kn0, kn1;
};
struct AllParams { SampleParams s[BATCH]; int slot_base; };
struct GammaParams { float g[BATCH]; int total_blocks; };

// --------------------- shared augmentation compute --------------------------
// Augmented image value for the float4 tile idx4 (bit-identical in both
// kernels; validated R4).
__device__ inline float4 compute_img4(const float* __restrict__ ib,
                                      const SampleParams& sp, int idx4) {
    const int d4 = idx4 & 31;
    const int w  = (idx4 >> 5) & 127;
    const int h  = idx4 >> 12;
    const int hs = sp.fh ? 127 - h : h;
    const int ws = sp.fw ? 127 - w : w;

    float4 vi;
    if (sp.z == 1.0f) {
        const int sd4 = sp.fd ? 31 - d4 : d4;
        const int s4  = (hs << 12) | (ws << 5) | sd4;
        float4 ti = reinterpret_cast<const float4*>(ib)[s4];
        vi = sp.fd ? make_float4(ti.w, ti.z, ti.y, ti.x) : ti;
    } else {
        const float z = sp.z;
        const float ch = (hs - 63.5f) / z + 63.5f;
        const float cw = (ws - 63.5f) / z + 63.5f;
        const int h0 = (int)floorf(ch), w0 = (int)floorf(cw);
        const float th = ch - (float)h0, tw = cw - (float)w0;
        float wh0 = (h0 >= 0 && h0 < NSIDE) ? (1.0f - th) : 0.0f;
        float wh1 = (h0 + 1 >= 0 && h0 + 1 < NSIDE) ? th : 0.0f;
        float ww0 = (w0 >= 0 && w0 < NSIDE) ? (1.0f - tw) : 0.0f;
        float ww1 = (w0 + 1 >= 0 && w0 + 1 < NSIDE) ? tw : 0.0f;
        int hc0 = min(max(h0, 0), 127), hc1 = min(max(h0 + 1, 0), 127);
        int wc0 = min(max(w0, 0), 127), wc1 = min(max(w0 + 1, 0), 127);

        float ri[4];
#pragma unroll
        for (int j = 0; j < 4; j++) {
            const int dd = 4 * d4 + j;
            const int ds = sp.fd ? 127 - dd : dd;
            const float cd = (ds - 63.5f) / z + 63.5f;
            const int d0 = (int)floorf(cd);
            const float td = cd - (float)d0;
            float wd0 = (d0 >= 0 && d0 < NSIDE) ? (1.0f - td) : 0.0f;
            float wd1 = (d0 + 1 >= 0 && d0 + 1 < NSIDE) ? td : 0.0f;
            int dc0 = min(max(d0, 0), 127), dc1 = min(max(d0 + 1, 0), 127);

            float h00 = wh0 * ib[(hc0 << 14) | (wc0 << 7) | dc0] + wh1 * ib[(hc1 << 14) | (wc0 << 7) | dc0];
            float h10 = wh0 * ib[(hc0 << 14) | (wc1 << 7) | dc0] + wh1 * ib[(hc1 << 14) | (wc1 << 7) | dc0];
            float h01 = wh0 * ib[(hc0 << 14) | (wc0 << 7) | dc1] + wh1 * ib[(hc1 << 14) | (wc0 << 7) | dc1];
            float h11 = wh0 * ib[(hc0 << 14) | (wc1 << 7) | dc1] + wh1 * ib[(hc1 << 14) | (wc1 << 7) | dc1];
            ri[j] = wd0 * (ww0 * h00 + ww1 * h10) + wd1 * (ww0 * h01 + ww1 * h11);
        }
        vi = make_float4(ri[0], ri[1], ri[2], ri[3]);
    }

    if (sp.stdv > 0.0f) {
        float* pv = &vi.x;
#pragma unroll
        for (int j = 0; j < 4; j++) {
            uint32_t o0, o1;
            tf2x32(sp.kn0, sp.kn1, 0u, (uint32_t)(4 * idx4 + j), o0, o1);
            float f = bits_to_unit(o0 ^ o1);
            const float lo = -0.99999994f;           // nextafter(-1, 0)
            float u = fmaxf(lo, f * 2.0f + lo);
            pv[j] += sp.stdv * (1.41421356f * erfinv_xla(u));
        }
    }
    return vi;
}

// ------------------------------ main kernel --------------------------------
// Handles slots [slot_base, slot_base + gridDim.y).
__global__ void __launch_bounds__(256)
aug_kernel(const float* __restrict__ img, const float* __restrict__ lbl,
           float* __restrict__ out_img, float* __restrict__ out_lbl,
           AllParams P) {
    const SampleParams sp = P.s[P.slot_base + blockIdx.y];
    const int b    = sp.b;
    const int idx4 = blockIdx.x * 256 + threadIdx.x;

    const float* ib = img + (size_t)b * NVOX;
    const float* lb = lbl + (size_t)b * NVOX;

    // ---- image ----
    float4 vi = compute_img4(ib, sp, idx4);

    // ---- label ----
    const int d4 = idx4 & 31;
    const int w  = (idx4 >> 5) & 127;
    const int h  = idx4 >> 12;
    const int hs = sp.fh ? 127 - h : h;
    const int ws = sp.fw ? 127 - w : w;

    float4 vl;
    if (sp.z == 1.0f) {
        const int sd4 = sp.fd ? 31 - d4 : d4;
        const int s4  = (hs << 12) | (ws << 5) | sd4;
        float4 tl = reinterpret_cast<const float4*>(lb)[s4];
        vl = sp.fd ? make_float4(tl.w, tl.z, tl.y, tl.x) : tl;
    } else {
        const float z = sp.z;
        const float ch = (hs - 63.5f) / z + 63.5f;
        const float cw = (ws - 63.5f) / z + 63.5f;
        const int rh = (int)rintf(ch), rw = (int)rintf(cw);
        const bool hv = (rh >= 0 && rh < NSIDE), wv = (rw >= 0 && rw < NSIDE);
        const int rhc = min(max(rh, 0), 127), rwc = min(max(rw, 0), 127);
        float rl[4];
#pragma unroll
        for (int j = 0; j < 4; j++) {
            const int dd = 4 * d4 + j;
            const int ds = sp.fd ? 127 - dd : dd;
            const float cd = (ds - 63.5f) / z + 63.5f;
            const int rd = (int)rintf(cd);
            const bool valid = hv && wv && (rd >= 0 && rd < NSIDE);
            const int rdc = min(max(rd, 0), 127);
            rl[j] = valid ? lb[(rhc << 14) | (rwc << 7) | rdc] : 0.0f;
        }
        vl = make_float4(rl[0], rl[1], rl[2], rl[3]);
    }

    reinterpret_cast<float4*>(out_lbl)[(size_t)b * NV4 + idx4] = vl;

    if (!sp.need_stats) {
        reinterpret_cast<float4*>(out_img)[(size_t)b * NV4 + idx4] = vi;
        return;
    }

    // gamma sample: skip out_img store (gamma kernel recomputes + writes once);
    // contribute to min/max stats only.
    float vmin = fminf(fminf(vi.x, vi.y), fminf(vi.z, vi.w));
    float vmax = fmaxf(fmaxf(vi.x, vi.y), fmaxf(vi.z, vi.w));
#pragma unroll
    for (int o = 16; o > 0; o >>= 1) {
        vmin = fminf(vmin, __shfl_down_sync(0xFFFFFFFFu, vmin, o));
        vmax = fmaxf(vmax, __shfl_down_sync(0xFFFFFFFFu, vmax, o));
    }
    __shared__ float smin[8], smax[8];
    int lane = threadIdx.x & 31, wid = threadIdx.x >> 5;
    if (lane == 0) { smin[wid] = vmin; smax[wid] = vmax; }
    __syncthreads();
    if (wid == 0) {
        vmin = (lane < 8) ? smin[lane] : F32_INF;
        vmax = (lane < 8) ? smax[lane] : -F32_INF;
#pragma unroll
        for (int o = 4; o > 0; o >>= 1) {
            vmin = fminf(vmin, __shfl_down_sync(0xFFFFFFFFu, vmin, o));
            vmax = fmaxf(vmax, __shfl_down_sync(0xFFFFFFFFu, vmax, o));
        }
        if (lane == 0) {
            atomicMax(&g_maxenc[b], encf(vmax));
            atomicMax(&g_negmin[b], ~encf(vmin));
        }
    }
}

// ------------------------------ gamma kernel --------------------------------
// Recomputes the augmented image (bit-identical, img re-read is L2-warm from
// the just-finished aug over the same sample), applies gamma, writes out_img
// exactly once. Self-resets stats for the next graph replay. Gamma samples
// occupy slots [0, gridDim.y).
__global__ void __launch_bounds__(256)
gamma_kernel(const float* __restrict__ img, float* __restrict__ out_img,
             AllParams P, GammaParams G) {
    const SampleParams sp = P.s[blockIdx.y];
    const int b     = sp.b;
    const float gam = G.g[blockIdx.y];
    const int idx4  = blockIdx.x * 256 + threadIdx.x;

    const float mn  = decf(~g_negmin[b]);
    const float mx  = decf(g_maxenc[b]);
    const float rng = mx - mn;
    const float inv = 1.0f / (rng + 1e-7f);

    float4 v = compute_img4(img + (size_t)b * NVOX, sp, idx4);
    float* pv = &v.x;
#pragma unroll
    for (int j = 0; j < 4; j++) {
        float xn = fminf(fmaxf((pv[j] - mn) * inv, 1e-6f), 1.0f);
        pv[j] = __powf(xn, gam) * rng + mn;
    }
    reinterpret_cast<float4*>(out_img)[(size_t)b * NV4 + idx4] = v;

    // last block resets stats + counter so the next graph replay starts clean
    __syncthreads();
    if (threadIdx.x == 0) {
        __threadfence();
        unsigned old = atomicAdd(&g_done, 1u);
        if (old == (unsigned)(G.total_blocks - 1)) {
            for (int i = 0; i < BATCH; i++) { g_maxenc[i] = 0u; g_negmin[i] = 0u; }
            __threadfence();
            g_done = 0u;
        }
    }
}

// ------------------------------- host side ----------------------------------
static inline uint32_t xor_bits_host(uint32_t k0, uint32_t k1, uint32_t c1) {
    uint32_t o0, o1;
    tf2x32(k0, k1, 0u, c1, o0, o1);
    return o0 ^ o1;
}

extern "C" void kernel_launch(void* const* d_in, const int* in_sizes, int n_in,
                              void* d_out, int out_size) {
    const float* img = (const float*)d_in[0];
    const float* lbl = (const float*)d_in[1];
    float* out_img = (float*)d_out;
    float* out_lbl = (float*)d_out + (size_t)BATCH * NVOX;

    SampleParams tmp[BATCH];
    float gam_of[BATCH];
    int n_gamma = 0;

    const float span_z = 1.0f - 0.7f;
    const float span_s = 0.2f - 0.0f;
    const float span_g = 1.2f - 0.8f;

    for (int b = 0; b < BATCH; b++) {
        uint32_t kb0, kb1;
        tf2x32(0u, 42u, 0u, (uint32_t)b, kb0, kb1);

        uint32_t sk0[5], sk1[5];
        for (int j = 0; j < 5; j++) tf2x32(kb0, kb1, 0u, (uint32_t)j, sk0[j], sk1[j]);
        // order: kd, kz, ks, kn, kg
        float u[6];
        for (int i = 0; i < 6; i++)
            u[i] = bits_to_unit(xor_bits_host(sk0[0], sk1[0], (uint32_t)i));

        float z = 1.0f;
        if (u[0] < 0.15f) {
            float f = bits_to_unit(xor_bits_host(sk0[1], sk1[1], 0u));
            z = fmaxf(0.7f, f * span_z + 0.7f);
        }
        float stdv = 0.0f;
        if (u[4] < 0.1f) {
            float f = bits_to_unit(xor_bits_host(sk0[2], sk1[2], 0u));
            stdv = fmaxf(0.0f, f * span_s + 0.0f);
        }
        float gam = 1.0f;
        if (u[5] < 0.1f) {
            float f = bits_to_unit(xor_bits_host(sk0[4], sk1[4], 0u));
            gam = fmaxf(0.8f, f * span_g + 0.8f);
        }

        tmp[b].z    = z;
        tmp[b].stdv = stdv;
        tmp[b].b    = b;
        tmp[b].fh   = (u[1] < 0.5f) ? 1 : 0;
        tmp[b].fw   = (u[2] < 0.5f) ? 1 : 0;
        tmp[b].fd   = (u[3] < 0.5f) ? 1 : 0;
        tmp[b].kn0  = sk0[3];
        tmp[b].kn1  = sk1[3];
        tmp[b].need_stats = (gam != 1.0f) ? 1 : 0;
        gam_of[b] = gam;
    }

    // slots: gamma samples FIRST [0, n_gamma), rest after
    AllParams P;
    GammaParams G;
    int slot = 0;
    for (int b = 0; b < BATCH; b++)
        if (tmp[b].need_stats) { G.g[slot] = gam_of[b]; P.s[slot++] = tmp[b]; }
    n_gamma = slot;
    for (int b = 0; b < BATCH; b++)
        if (!tmp[b].need_stats) P.s[slot++] = tmp[b];
    const int n_rest = BATCH - n_gamma;

    if (n_gamma == 0) {
        AllParams Pa = P; Pa.slot_base = 0;
        dim3 grid(NV4 / 256, BATCH);
        aug_kernel<<<grid, 256>>>(img, lbl, out_img, out_lbl, Pa);
        return;
    }

    if (n_rest == 0) {
        // all samples need gamma: sequential aug -> gamma
        AllParams Pa = P; Pa.slot_base = 0;
        dim3 grid(NV4 / 256, BATCH);
        aug_kernel<<<grid, 256>>>(img, lbl, out_img, out_lbl, Pa);
        dim3 ggrid(NV4 / 256, n_gamma);
        G.total_blocks = (int)(ggrid.x * ggrid.y);
        gamma_kernel<<<ggrid, 256>>>(img, out_img, Pa, G);
        return;
    }

    // fork-join: gamma samples' aug + gamma recompute on the capture stream,
    // remaining samples concurrently on a forked stream.
    cudaStream_t s2;
    cudaEvent_t evFork, evJoin;
    cudaStreamCreateWithFlags(&s2, cudaStreamNonBlocking);
    cudaEventCreateWithFlags(&evFork, cudaEventDisableTiming);
    cudaEventCreateWithFlags(&evJoin, cudaEventDisableTiming);

    cudaEventRecord(evFork, 0);
    cudaStreamWaitEvent(s2, evFork, 0);

    // stream2: the non-gamma samples
    {
        AllParams Pr = P; Pr.slot_base = n_gamma;
        dim3 grid(NV4 / 256, n_rest);
        aug_kernel<<<grid, 256, 0, s2>>>(img, lbl, out_img, out_lbl, Pr);
        cudaEventRecord(evJoin, s2);
    }

    // capture stream: gamma samples' aug (stats + lbl only), then gamma
    // (recompute; img L2-warm), overlapping with stream2
    {
        AllParams Pg = P; Pg.slot_base = 0;
        dim3 grid(NV4 / 256, n_gamma);
        aug_kernel<<<grid, 256>>>(img, lbl, out_img, out_lbl, Pg);
        dim3 ggrid(NV4 / 256, n_gamma);
        G.total_blocks = (int)(ggrid.x * ggrid.y);
        gamma_kernel<<<ggrid, 256>>>(img, out_img, Pg, G);
    }

    cudaStreamWaitEvent(0, evJoin, 0);
}

// round 9
// speedup vs baseline: 1.0880x; 1.0880x over previous
#include <cuda_runtime.h>
#include <cstdint>
#include <cstring>
#include <math.h>

// ---------------------------------------------------------------------------
// DataAugmenter: zoom(linear/nearest) -> flips -> gaussian noise -> gamma.
// JAX threefry2x32, threefry_partitionable=True (validated R2).
// R9 = R7 (fork-join overlap, gamma reads out_img) +
//      2 float4/thread in aug (higher MLP) +
//      __stcs streaming stores for never-re-read outputs (L2 protection).
// ---------------------------------------------------------------------------

static const int BATCH = 8;
static const int NSIDE = 128;
static const int NVOX  = NSIDE * NSIDE * NSIDE;   // 2^21 per sample
static const int NV4   = NVOX / 4;                // float4 per sample
static const int A_UNROLL = 2;                    // float4s per aug thread

#define F32_INF __int_as_float(0x7F800000)

// ----------------------------- threefry2x32 --------------------------------
__host__ __device__ inline uint32_t rotl32(uint32_t v, int d) {
    return (v << d) | (v >> (32 - d));
}

__host__ __device__ inline void tf2x32(uint32_t k0, uint32_t k1,
                                       uint32_t c0, uint32_t c1,
                                       uint32_t& o0, uint32_t& o1) {
    uint32_t ks0 = k0, ks1 = k1, ks2 = 0x1BD11BDAu ^ k0 ^ k1;
    uint32_t x0 = c0 + ks0, x1 = c1 + ks1;
#define TFR(r) { x0 += x1; x1 = rotl32(x1, r); x1 ^= x0; }
    TFR(13) TFR(15) TFR(26) TFR(6)
    x0 += ks1; x1 += ks2 + 1u;
    TFR(17) TFR(29) TFR(16) TFR(24)
    x0 += ks2; x1 += ks0 + 2u;
    TFR(13) TFR(15) TFR(26) TFR(6)
    x0 += ks0; x1 += ks1 + 3u;
    TFR(17) TFR(29) TFR(16) TFR(24)
    x0 += ks1; x1 += ks2 + 4u;
    TFR(13) TFR(15) TFR(26) TFR(6)
    x0 += ks2; x1 += ks0 + 5u;
#undef TFR
    o0 = x0; o1 = x1;
}

__host__ __device__ inline float bits_to_unit(uint32_t bits) {
    uint32_t fb = (bits >> 9) | 0x3F800000u;
    float f;
#ifdef __CUDA_ARCH__
    f = __uint_as_float(fb);
#else
    memcpy(&f, &fb, 4);
#endif
    return f - 1.0f;
}

// XLA f32 ErfInv (Giles polynomial)
__device__ inline float erfinv_xla(float x) {
    float w = -log1pf(-x * x);
    float p;
    if (w < 5.0f) {
        w = w - 2.5f;
        p = 2.81022636e-08f;
        p = fmaf(p, w, 3.43273939e-07f);
        p = fmaf(p, w, -3.5233877e-06f);
        p = fmaf(p, w, -4.39150654e-06f);
        p = fmaf(p, w, 0.00021858087f);
        p = fmaf(p, w, -0.00125372503f);
        p = fmaf(p, w, -0.00417768164f);
        p = fmaf(p, w, 0.246640727f);
        p = fmaf(p, w, 1.50140941f);
    } else {
        w = sqrtf(w) - 3.0f;
        p = -0.000200214257f;
        p = fmaf(p, w, 0.000100950558f);
        p = fmaf(p, w, 0.00134934322f);
        p = fmaf(p, w, -0.00367342844f);
        p = fmaf(p, w, 0.00573950773f);
        p = fmaf(p, w, -0.0076224613f);
        p = fmaf(p, w, 0.00943887047f);
        p = fmaf(p, w, 1.00167406f);
        p = fmaf(p, w, 2.83297682f);
    }
    return p * x;
}

// ----------------------- ordered-uint min/max encoding ----------------------
__device__ inline unsigned encf(float f) {
    unsigned u = __float_as_uint(f);
    return (u & 0x80000000u) ? ~u : (u | 0x80000000u);
}
__device__ inline float decf(unsigned e) {
    unsigned u = (e & 0x80000000u) ? (e ^ 0x80000000u) : ~e;
    return __uint_as_float(u);
}

// Stats via atomicMax with identity 0 (zero-init compatible):
// max as encf(v), min as ~encf(v).
__device__ unsigned g_maxenc[BATCH];
__device__ unsigned g_negmin[BATCH];
__device__ unsigned g_done;

// ------------------------------- params ------------------------------------
struct SampleParams {
    float z;
    float stdv;
    int b;            // actual sample index
    int fh, fw, fd;
    int need_stats;
    uint32_t kn0, kn1;
};
struct AllParams { SampleParams s[BATCH]; int slot_base; };
struct GammaParams { int sid[BATCH]; float g[BATCH]; int total_blocks; };

// --------------------- per-tile augmentation compute ------------------------
__device__ inline void compute_tile(const float* __restrict__ ib,
                                    const float* __restrict__ lb,
                                    const SampleParams& sp, int idx4,
                                    float4& vi, float4& vl) {
    const int d4 = idx4 & 31;
    const int w  = (idx4 >> 5) & 127;
    const int h  = idx4 >> 12;
    const int hs = sp.fh ? 127 - h : h;
    const int ws = sp.fw ? 127 - w : w;

    if (sp.z == 1.0f) {
        const int sd4 = sp.fd ? 31 - d4 : d4;
        const int s4  = (hs << 12) | (ws << 5) | sd4;
        float4 ti = reinterpret_cast<const float4*>(ib)[s4];
        float4 tl = reinterpret_cast<const float4*>(lb)[s4];
        if (sp.fd) {
            vi = make_float4(ti.w, ti.z, ti.y, ti.x);
            vl = make_float4(tl.w, tl.z, tl.y, tl.x);
        } else {
            vi = ti; vl = tl;
        }
    } else {
        const float z = sp.z;
        const float ch = (hs - 63.5f) / z + 63.5f;
        const float cw = (ws - 63.5f) / z + 63.5f;
        const int h0 = (int)floorf(ch), w0 = (int)floorf(cw);
        const float th = ch - (float)h0, tw = cw - (float)w0;
        float wh0 = (h0 >= 0 && h0 < NSIDE) ? (1.0f - th) : 0.0f;
        float wh1 = (h0 + 1 >= 0 && h0 + 1 < NSIDE) ? th : 0.0f;
        float ww0 = (w0 >= 0 && w0 < NSIDE) ? (1.0f - tw) : 0.0f;
        float ww1 = (w0 + 1 >= 0 && w0 + 1 < NSIDE) ? tw : 0.0f;
        int hc0 = min(max(h0, 0), 127), hc1 = min(max(h0 + 1, 0), 127);
        int wc0 = min(max(w0, 0), 127), wc1 = min(max(w0 + 1, 0), 127);
        const int rh = (int)rintf(ch), rw = (int)rintf(cw);
        const bool hv = (rh >= 0 && rh < NSIDE), wv = (rw >= 0 && rw < NSIDE);
        const int rhc = min(max(rh, 0), 127), rwc = min(max(rw, 0), 127);

        float ri[4], rl[4];
#pragma unroll
        for (int j = 0; j < 4; j++) {
            const int dd = 4 * d4 + j;
            const int ds = sp.fd ? 127 - dd : dd;
            const float cd = (ds - 63.5f) / z + 63.5f;
            const int d0 = (int)floorf(cd);
            const float td = cd - (float)d0;
            float wd0 = (d0 >= 0 && d0 < NSIDE) ? (1.0f - td) : 0.0f;
            float wd1 = (d0 + 1 >= 0 && d0 + 1 < NSIDE) ? td : 0.0f;
            int dc0 = min(max(d0, 0), 127), dc1 = min(max(d0 + 1, 0), 127);

            float h00 = wh0 * ib[(hc0 << 14) | (wc0 << 7) | dc0] + wh1 * ib[(hc1 << 14) | (wc0 << 7) | dc0];
            float h10 = wh0 * ib[(hc0 << 14) | (wc1 << 7) | dc0] + wh1 * ib[(hc1 << 14) | (wc1 << 7) | dc0];
            float h01 = wh0 * ib[(hc0 << 14) | (wc0 << 7) | dc1] + wh1 * ib[(hc1 << 14) | (wc0 << 7) | dc1];
            float h11 = wh0 * ib[(hc0 << 14) | (wc1 << 7) | dc1] + wh1 * ib[(hc1 << 14) | (wc1 << 7) | dc1];
            ri[j] = wd0 * (ww0 * h00 + ww1 * h10) + wd1 * (ww0 * h01 + ww1 * h11);

            const int rd = (int)rintf(cd);
            const bool valid = hv && wv && (rd >= 0 && rd < NSIDE);
            const int rdc = min(max(rd, 0), 127);
            rl[j] = valid ? lb[(rhc << 14) | (rwc << 7) | rdc] : 0.0f;
        }
        vi = make_float4(ri[0], ri[1], ri[2], ri[3]);
        vl = make_float4(rl[0], rl[1], rl[2], rl[3]);
    }

    if (sp.stdv > 0.0f) {
        float* pv = &vi.x;
#pragma unroll
        for (int j = 0; j < 4; j++) {
            uint32_t o0, o1;
            tf2x32(sp.kn0, sp.kn1, 0u, (uint32_t)(4 * idx4 + j), o0, o1);
            float f = bits_to_unit(o0 ^ o1);
            const float lo = -0.99999994f;           // nextafter(-1, 0)
            float u = fmaxf(lo, f * 2.0f + lo);
            pv[j] += sp.stdv * (1.41421356f * erfinv_xla(u));
        }
    }
}

// ------------------------------ main kernel --------------------------------
// A_UNROLL float4 tiles per thread. Handles slots [slot_base, +gridDim.y).
__global__ void __launch_bounds__(256)
aug_kernel(const float* __restrict__ img, const float* __restrict__ lbl,
           float* __restrict__ out_img, float* __restrict__ out_lbl,
           AllParams P) {
    const SampleParams sp = P.s[P.slot_base + blockIdx.y];
    const int b     = sp.b;
    const int base4 = blockIdx.x * (256 * A_UNROLL) + threadIdx.x;

    const float* ib = img + (size_t)b * NVOX;
    const float* lb = lbl + (size_t)b * NVOX;
    float4* oi = reinterpret_cast<float4*>(out_img) + (size_t)b * NV4;
    float4* ol = reinterpret_cast<float4*>(out_lbl) + (size_t)b * NV4;

    float4 vi[A_UNROLL], vl[A_UNROLL];
#pragma unroll
    for (int k = 0; k < A_UNROLL; k++)
        compute_tile(ib, lb, sp, base4 + k * 256, vi[k], vl[k]);

#pragma unroll
    for (int k = 0; k < A_UNROLL; k++)
        __stcs(ol + base4 + k * 256, vl[k]);      // labels never re-read

    if (!sp.need_stats) {
#pragma unroll
        for (int k = 0; k < A_UNROLL; k++)
            __stcs(oi + base4 + k * 256, vi[k]);  // not re-read either
        return;
    }

    // gamma sample: default-policy store (gamma kernel re-reads from L2)
#pragma unroll
    for (int k = 0; k < A_UNROLL; k++)
        oi[base4 + k * 256] = vi[k];

    float vmin = F32_INF, vmax = -F32_INF;
#pragma unroll
    for (int k = 0; k < A_UNROLL; k++) {
        vmin = fminf(vmin, fminf(fminf(vi[k].x, vi[k].y), fminf(vi[k].z, vi[k].w)));
        vmax = fmaxf(vmax, fmaxf(fmaxf(vi[k].x, vi[k].y), fmaxf(vi[k].z, vi[k].w)));
    }
#pragma unroll
    for (int o = 16; o > 0; o >>= 1) {
        vmin = fminf(vmin, __shfl_down_sync(0xFFFFFFFFu, vmin, o));
        vmax = fmaxf(vmax, __shfl_down_sync(0xFFFFFFFFu, vmax, o));
    }
    __shared__ float smin[8], smax[8];
    int lane = threadIdx.x & 31, wid = threadIdx.x >> 5;
    if (lane == 0) { smin[wid] = vmin; smax[wid] = vmax; }
    __syncthreads();
    if (wid == 0) {
        vmin = (lane < 8) ? smin[lane] : F32_INF;
        vmax = (lane < 8) ? smax[lane] : -F32_INF;
#pragma unroll
        for (int o = 4; o > 0; o >>= 1) {
            vmin = fminf(vmin, __shfl_down_sync(0xFFFFFFFFu, vmin, o));
            vmax = fmaxf(vmax, __shfl_down_sync(0xFFFFFFFFu, vmax, o));
        }
        if (lane == 0) {
            atomicMax(&g_maxenc[b], encf(vmax));
            atomicMax(&g_negmin[b], ~encf(vmin));
        }
    }
}

// ------------------------------ gamma kernel --------------------------------
// 2 float4/thread. Reads out_img (L2-resident: written by the immediately
// preceding aug over only the gamma samples), gamma, writes back (final,
// never re-read -> streaming store). Self-resets stats for next replay.
static const int G_UNROLL = 2;
__global__ void __launch_bounds__(256)
gamma_kernel(float* __restrict__ out_img, GammaParams G) {
    const int b     = G.sid[blockIdx.y];
    const float gam = G.g[blockIdx.y];
    const int base  = blockIdx.x * (256 * G_UNROLL) + threadIdx.x;

    const float mn  = decf(~g_negmin[b]);
    const float mx  = decf(g_maxenc[b]);
    const float rng = mx - mn;
    const float inv = 1.0f / (rng + 1e-7f);

    float4* p = reinterpret_cast<float4*>(out_img) + (size_t)b * NV4;

    float4 v[G_UNROLL];
#pragma unroll
    for (int k = 0; k < G_UNROLL; k++)
        v[k] = p[base + k * 256];

#pragma unroll
    for (int k = 0; k < G_UNROLL; k++) {
        float* pv = &v[k].x;
#pragma unroll
        for (int j = 0; j < 4; j++) {
            float xn = fminf(fmaxf((pv[j] - mn) * inv, 1e-6f), 1.0f);
            pv[j] = __powf(xn, gam) * rng + mn;
        }
    }

#pragma unroll
    for (int k = 0; k < G_UNROLL; k++)
        __stcs(p + base + k * 256, v[k]);

    // last block resets stats + counter so the next graph replay starts clean
    __syncthreads();
    if (threadIdx.x == 0) {
        __threadfence();
        unsigned old = atomicAdd(&g_done, 1u);
        if (old == (unsigned)(G.total_blocks - 1)) {
            for (int i = 0; i < BATCH; i++) { g_maxenc[i] = 0u; g_negmin[i] = 0u; }
            __threadfence();
            g_done = 0u;
        }
    }
}

// ------------------------------- host side ----------------------------------
static inline uint32_t xor_bits_host(uint32_t k0, uint32_t k1, uint32_t c1) {
    uint32_t o0, o1;
    tf2x32(k0, k1, 0u, c1, o0, o1);
    return o0 ^ o1;
}

extern "C" void kernel_launch(void* const* d_in, const int* in_sizes, int n_in,
                              void* d_out, int out_size) {
    const float* img = (const float*)d_in[0];
    const float* lbl = (const float*)d_in[1];
    float* out_img = (float*)d_out;
    float* out_lbl = (float*)d_out + (size_t)BATCH * NVOX;

    SampleParams tmp[BATCH];
    GammaParams G;
    int n_gamma = 0;

    const float span_z = 1.0f - 0.7f;
    const float span_s = 0.2f - 0.0f;
    const float span_g = 1.2f - 0.8f;

    for (int b = 0; b < BATCH; b++) {
        uint32_t kb0, kb1;
        tf2x32(0u, 42u, 0u, (uint32_t)b, kb0, kb1);

        uint32_t sk0[5], sk1[5];
        for (int j = 0; j < 5; j++) tf2x32(kb0, kb1, 0u, (uint32_t)j, sk0[j], sk1[j]);
        // order: kd, kz, ks, kn, kg
        float u[6];
        for (int i = 0; i < 6; i++)
            u[i] = bits_to_unit(xor_bits_host(sk0[0], sk1[0], (uint32_t)i));

        float z = 1.0f;
        if (u[0] < 0.15f) {
            float f = bits_to_unit(xor_bits_host(sk0[1], sk1[1], 0u));
            z = fmaxf(0.7f, f * span_z + 0.7f);
        }
        float stdv = 0.0f;
        if (u[4] < 0.1f) {
            float f = bits_to_unit(xor_bits_host(sk0[2], sk1[2], 0u));
            stdv = fmaxf(0.0f, f * span_s + 0.0f);
        }
        float gam = 1.0f;
        if (u[5] < 0.1f) {
            float f = bits_to_unit(xor_bits_host(sk0[4], sk1[4], 0u));
            gam = fmaxf(0.8f, f * span_g + 0.8f);
        }

        tmp[b].z    = z;
        tmp[b].stdv = stdv;
        tmp[b].b    = b;
        tmp[b].fh   = (u[1] < 0.5f) ? 1 : 0;
        tmp[b].fw   = (u[2] < 0.5f) ? 1 : 0;
        tmp[b].fd   = (u[3] < 0.5f) ? 1 : 0;
        tmp[b].kn0  = sk0[3];
        tmp[b].kn1  = sk1[3];
        tmp[b].need_stats = (gam != 1.0f) ? 1 : 0;
        if (gam != 1.0f) {
            G.sid[n_gamma] = b;
            G.g[n_gamma]   = gam;
            n_gamma++;
        }
    }

    // slots: gamma samples FIRST [0, n_gamma), rest after
    AllParams P;
    int slot = 0;
    for (int b = 0; b < BATCH; b++) if (tmp[b].need_stats)  P.s[slot++] = tmp[b];
    for (int b = 0; b < BATCH; b++) if (!tmp[b].need_stats) P.s[slot++] = tmp[b];
    const int n_rest = BATCH - n_gamma;

    const int GX = NV4 / (256 * A_UNROLL);

    if (n_gamma == 0 || n_rest == 0) {
        AllParams Pa = P; Pa.slot_base = 0;
        dim3 grid(GX, BATCH);
        aug_kernel<<<grid, 256>>>(img, lbl, out_img, out_lbl, Pa);
        if (n_gamma > 0) {
            dim3 ggrid(NV4 / (256 * G_UNROLL), n_gamma);
            G.total_blocks = (int)(ggrid.x * ggrid.y);
            gamma_kernel<<<ggrid, 256>>>(out_img, G);
        }
        return;
    }

    // fork-join: gamma samples + gamma kernel on the capture stream,
    // remaining samples concurrently on a forked stream.
    cudaStream_t s2;
    cudaEvent_t evFork, evJoin;
    cudaStreamCreateWithFlags(&s2, cudaStreamNonBlocking);
    cudaEventCreateWithFlags(&evFork, cudaEventDisableTiming);
    cudaEventCreateWithFlags(&evJoin, cudaEventDisableTiming);

    cudaEventRecord(evFork, 0);
    cudaStreamWaitEvent(s2, evFork, 0);

    // stream2: the non-gamma samples
    {
        AllParams Pr = P; Pr.slot_base = n_gamma;
        dim3 grid(GX, n_rest);
        aug_kernel<<<grid, 256, 0, s2>>>(img, lbl, out_img, out_lbl, Pr);
        cudaEventRecord(evJoin, s2);
    }

    // capture stream: gamma samples' aug, then gamma (input hot in L2)
    {
        AllParams Pg = P; Pg.slot_base = 0;
        dim3 grid(GX, n_gamma);
        aug_kernel<<<grid, 256>>>(img, lbl, out_img, out_lbl, Pg);
        dim3 ggrid(NV4 / (256 * G_UNROLL), n_gamma);
        G.total_blocks = (int)(ggrid.x * ggrid.y);
        gamma_kernel<<<ggrid, 256>>>(out_img, G);
    }

    cudaStreamWaitEvent(0, evJoin, 0);
}

// round 10
// speedup vs baseline: 1.1248x; 1.0338x over previous
#include <cuda_runtime.h>
#include <cstdint>
#include <cstring>
#include <math.h>

// ---------------------------------------------------------------------------
// DataAugmenter: zoom(linear/nearest) -> flips -> gaussian noise -> gamma.
// JAX threefry2x32, threefry_partitionable=True (validated R2).
// R10 = R7 (best, 49.2us: fork-join overlap, A_UNROLL=1, gamma reads out_img)
//       + ONE isolated change: __stcs streaming stores for label outputs
//       (never re-read; frees L2 write-allocate footprint).
// ---------------------------------------------------------------------------

static const int BATCH = 8;
static const int NSIDE = 128;
static const int NVOX  = NSIDE * NSIDE * NSIDE;   // 2^21 per sample
static const int NV4   = NVOX / 4;                // float4 per sample

#define F32_INF __int_as_float(0x7F800000)

// ----------------------------- threefry2x32 --------------------------------
__host__ __device__ inline uint32_t rotl32(uint32_t v, int d) {
    return (v << d) | (v >> (32 - d));
}

__host__ __device__ inline void tf2x32(uint32_t k0, uint32_t k1,
                                       uint32_t c0, uint32_t c1,
                                       uint32_t& o0, uint32_t& o1) {
    uint32_t ks0 = k0, ks1 = k1, ks2 = 0x1BD11BDAu ^ k0 ^ k1;
    uint32_t x0 = c0 + ks0, x1 = c1 + ks1;
#define TFR(r) { x0 += x1; x1 = rotl32(x1, r); x1 ^= x0; }
    TFR(13) TFR(15) TFR(26) TFR(6)
    x0 += ks1; x1 += ks2 + 1u;
    TFR(17) TFR(29) TFR(16) TFR(24)
    x0 += ks2; x1 += ks0 + 2u;
    TFR(13) TFR(15) TFR(26) TFR(6)
    x0 += ks0; x1 += ks1 + 3u;
    TFR(17) TFR(29) TFR(16) TFR(24)
    x0 += ks1; x1 += ks2 + 4u;
    TFR(13) TFR(15) TFR(26) TFR(6)
    x0 += ks2; x1 += ks0 + 5u;
#undef TFR
    o0 = x0; o1 = x1;
}

__host__ __device__ inline float bits_to_unit(uint32_t bits) {
    uint32_t fb = (bits >> 9) | 0x3F800000u;
    float f;
#ifdef __CUDA_ARCH__
    f = __uint_as_float(fb);
#else
    memcpy(&f, &fb, 4);
#endif
    return f - 1.0f;
}

// XLA f32 ErfInv (Giles polynomial)
__device__ inline float erfinv_xla(float x) {
    float w = -log1pf(-x * x);
    float p;
    if (w < 5.0f) {
        w = w - 2.5f;
        p = 2.81022636e-08f;
        p = fmaf(p, w, 3.43273939e-07f);
        p = fmaf(p, w, -3.5233877e-06f);
        p = fmaf(p, w, -4.39150654e-06f);
        p = fmaf(p, w, 0.00021858087f);
        p = fmaf(p, w, -0.00125372503f);
        p = fmaf(p, w, -0.00417768164f);
        p = fmaf(p, w, 0.246640727f);
        p = fmaf(p, w, 1.50140941f);
    } else {
        w = sqrtf(w) - 3.0f;
        p = -0.000200214257f;
        p = fmaf(p, w, 0.000100950558f);
        p = fmaf(p, w, 0.00134934322f);
        p = fmaf(p, w, -0.00367342844f);
        p = fmaf(p, w, 0.00573950773f);
        p = fmaf(p, w, -0.0076224613f);
        p = fmaf(p, w, 0.00943887047f);
        p = fmaf(p, w, 1.00167406f);
        p = fmaf(p, w, 2.83297682f);
    }
    return p * x;
}

// ----------------------- ordered-uint min/max encoding ----------------------
__device__ inline unsigned encf(float f) {
    unsigned u = __float_as_uint(f);
    return (u & 0x80000000u) ? ~u : (u | 0x80000000u);
}
__device__ inline float decf(unsigned e) {
    unsigned u = (e & 0x80000000u) ? (e ^ 0x80000000u) : ~e;
    return __uint_as_float(u);
}

// Stats via atomicMax with identity 0 (zero-init compatible):
// max as encf(v), min as ~encf(v).
__device__ unsigned g_maxenc[BATCH];
__device__ unsigned g_negmin[BATCH];
__device__ unsigned g_done;

// ------------------------------- params ------------------------------------
struct SampleParams {
    float z;
    float stdv;
    int b;            // actual sample index
    int fh, fw, fd;
    int need_stats;
    uint32_t kn0, kn1;
};
struct AllParams { SampleParams s[BATCH]; int slot_base; };
struct GammaParams { int sid[BATCH]; float g[BATCH]; int total_blocks; };

// ------------------------------ main kernel --------------------------------
// One thread = 4 consecutive d-voxels (one float4).
// Handles slots [slot_base, slot_base + gridDim.y).
__global__ void __launch_bounds__(256)
aug_kernel(const float* __restrict__ img, const float* __restrict__ lbl,
           float* __restrict__ out_img, float* __restrict__ out_lbl,
           AllParams P) {
    const SampleParams sp = P.s[P.slot_base + blockIdx.y];
    const int b    = sp.b;
    const int idx4 = blockIdx.x * 256 + threadIdx.x;

    const int d4 = idx4 & 31;
    const int w  = (idx4 >> 5) & 127;
    const int h  = idx4 >> 12;
    const int hs = sp.fh ? 127 - h : h;
    const int ws = sp.fw ? 127 - w : w;

    const float* ib = img + (size_t)b * NVOX;
    const float* lb = lbl + (size_t)b * NVOX;

    float4 vi, vl;

    if (sp.z == 1.0f) {
        const int sd4 = sp.fd ? 31 - d4 : d4;
        const int s4  = (hs << 12) | (ws << 5) | sd4;
        float4 ti = reinterpret_cast<const float4*>(ib)[s4];
        float4 tl = reinterpret_cast<const float4*>(lb)[s4];
        if (sp.fd) {
            vi = make_float4(ti.w, ti.z, ti.y, ti.x);
            vl = make_float4(tl.w, tl.z, tl.y, tl.x);
        } else {
            vi = ti; vl = tl;
        }
    } else {
        const float z = sp.z;
        const float ch = (hs - 63.5f) / z + 63.5f;
        const float cw = (ws - 63.5f) / z + 63.5f;
        const int h0 = (int)floorf(ch), w0 = (int)floorf(cw);
        const float th = ch - (float)h0, tw = cw - (float)w0;
        float wh0 = (h0 >= 0 && h0 < NSIDE) ? (1.0f - th) : 0.0f;
        float wh1 = (h0 + 1 >= 0 && h0 + 1 < NSIDE) ? th : 0.0f;
        float ww0 = (w0 >= 0 && w0 < NSIDE) ? (1.0f - tw) : 0.0f;
        float ww1 = (w0 + 1 >= 0 && w0 + 1 < NSIDE) ? tw : 0.0f;
        int hc0 = min(max(h0, 0), 127), hc1 = min(max(h0 + 1, 0), 127);
        int wc0 = min(max(w0, 0), 127), wc1 = min(max(w0 + 1, 0), 127);
        const int rh = (int)rintf(ch), rw = (int)rintf(cw);
        const bool hv = (rh >= 0 && rh < NSIDE), wv = (rw >= 0 && rw < NSIDE);
        const int rhc = min(max(rh, 0), 127), rwc = min(max(rw, 0), 127);

        float ri[4], rl[4];
#pragma unroll
        for (int j = 0; j < 4; j++) {
            const int dd = 4 * d4 + j;
            const int ds = sp.fd ? 127 - dd : dd;
            const float cd = (ds - 63.5f) / z + 63.5f;
            const int d0 = (int)floorf(cd);
            const float td = cd - (float)d0;
            float wd0 = (d0 >= 0 && d0 < NSIDE) ? (1.0f - td) : 0.0f;
            float wd1 = (d0 + 1 >= 0 && d0 + 1 < NSIDE) ? td : 0.0f;
            int dc0 = min(max(d0, 0), 127), dc1 = min(max(d0 + 1, 0), 127);

            float h00 = wh0 * ib[(hc0 << 14) | (wc0 << 7) | dc0] + wh1 * ib[(hc1 << 14) | (wc0 << 7) | dc0];
            float h10 = wh0 * ib[(hc0 << 14) | (wc1 << 7) | dc0] + wh1 * ib[(hc1 << 14) | (wc1 << 7) | dc0];
            float h01 = wh0 * ib[(hc0 << 14) | (wc0 << 7) | dc1] + wh1 * ib[(hc1 << 14) | (wc0 << 7) | dc1];
            float h11 = wh0 * ib[(hc0 << 14) | (wc1 << 7) | dc1] + wh1 * ib[(hc1 << 14) | (wc1 << 7) | dc1];
            ri[j] = wd0 * (ww0 * h00 + ww1 * h10) + wd1 * (ww0 * h01 + ww1 * h11);

            const int rd = (int)rintf(cd);
            const bool valid = hv && wv && (rd >= 0 && rd < NSIDE);
            const int rdc = min(max(rd, 0), 127);
            rl[j] = valid ? lb[(rhc << 14) | (rwc << 7) | rdc] : 0.0f;
        }
        vi = make_float4(ri[0], ri[1], ri[2], ri[3]);
        vl = make_float4(rl[0], rl[1], rl[2], rl[3]);
    }

    if (sp.stdv > 0.0f) {
        float* pv = &vi.x;
#pragma unroll
        for (int j = 0; j < 4; j++) {
            uint32_t o0, o1;
            tf2x32(sp.kn0, sp.kn1, 0u, (uint32_t)(4 * idx4 + j), o0, o1);
            float f = bits_to_unit(o0 ^ o1);
            const float lo = -0.99999994f;           // nextafter(-1, 0)
            float u = fmaxf(lo, f * 2.0f + lo);
            pv[j] += sp.stdv * (1.41421356f * erfinv_xla(u));
        }
    }

    reinterpret_cast<float4*>(out_img)[(size_t)b * NV4 + idx4] = vi;
    // labels are never re-read -> streaming store (the ONE change vs R7)
    __stcs(reinterpret_cast<float4*>(out_lbl) + (size_t)b * NV4 + idx4, vl);

    if (sp.need_stats) {
        float vmin = fminf(fminf(vi.x, vi.y), fminf(vi.z, vi.w));
        float vmax = fmaxf(fmaxf(vi.x, vi.y), fmaxf(vi.z, vi.w));
#pragma unroll
        for (int o = 16; o > 0; o >>= 1) {
            vmin = fminf(vmin, __shfl_down_sync(0xFFFFFFFFu, vmin, o));
            vmax = fmaxf(vmax, __shfl_down_sync(0xFFFFFFFFu, vmax, o));
        }
        __shared__ float smin[8], smax[8];
        int lane = threadIdx.x & 31, wid = threadIdx.x >> 5;
        if (lane == 0) { smin[wid] = vmin; smax[wid] = vmax; }
        __syncthreads();
        if (wid == 0) {
            vmin = (lane < 8) ? smin[lane] : F32_INF;
            vmax = (lane < 8) ? smax[lane] : -F32_INF;
#pragma unroll
            for (int o = 4; o > 0; o >>= 1) {
                vmin = fminf(vmin, __shfl_down_sync(0xFFFFFFFFu, vmin, o));
                vmax = fmaxf(vmax, __shfl_down_sync(0xFFFFFFFFu, vmax, o));
            }
            if (lane == 0) {
                atomicMax(&g_maxenc[b], encf(vmax));
                atomicMax(&g_negmin[b], ~encf(vmin));
            }
        }
    }
}

// ------------------------------ gamma kernel --------------------------------
// 2 float4/thread. Reads out_img (L2-resident), gamma, writes back.
// Self-resets device stats for the next graph replay.
static const int G_UNROLL = 2;
__global__ void __launch_bounds__(256)
gamma_kernel(float* __restrict__ out_img, GammaParams G) {
    const int b     = G.sid[blockIdx.y];
    const float gam = G.g[blockIdx.y];
    const int base  = blockIdx.x * (256 * G_UNROLL) + threadIdx.x;

    const float mn  = decf(~g_negmin[b]);
    const float mx  = decf(g_maxenc[b]);
    const float rng = mx - mn;
    const float inv = 1.0f / (rng + 1e-7f);

    float4* p = reinterpret_cast<float4*>(out_img) + (size_t)b * NV4;

    float4 v[G_UNROLL];
#pragma unroll
    for (int k = 0; k < G_UNROLL; k++)
        v[k] = p[base + k * 256];

#pragma unroll
    for (int k = 0; k < G_UNROLL; k++) {
        float* pv = &v[k].x;
#pragma unroll
        for (int j = 0; j < 4; j++) {
            float xn = fminf(fmaxf((pv[j] - mn) * inv, 1e-6f), 1.0f);
            pv[j] = __powf(xn, gam) * rng + mn;
        }
    }

#pragma unroll
    for (int k = 0; k < G_UNROLL; k++)
        __stcs(p + base + k * 256, v[k]);   // final output, never re-read

    // last block resets stats + counter so the next graph replay starts clean
    __syncthreads();
    if (threadIdx.x == 0) {
        __threadfence();
        unsigned old = atomicAdd(&g_done, 1u);
        if (old == (unsigned)(G.total_blocks - 1)) {
            for (int i = 0; i < BATCH; i++) { g_maxenc[i] = 0u; g_negmin[i] = 0u; }
            __threadfence();
            g_done = 0u;
        }
    }
}

// ------------------------------- host side ----------------------------------
static inline uint32_t xor_bits_host(uint32_t k0, uint32_t k1, uint32_t c1) {
    uint32_t o0, o1;
    tf2x32(k0, k1, 0u, c1, o0, o1);
    return o0 ^ o1;
}

extern "C" void kernel_launch(void* const* d_in, const int* in_sizes, int n_in,
                              void* d_out, int out_size) {
    const float* img = (const float*)d_in[0];
    const float* lbl = (const float*)d_in[1];
    float* out_img = (float*)d_out;
    float* out_lbl = (float*)d_out + (size_t)BATCH * NVOX;

    SampleParams tmp[BATCH];
    GammaParams G;
    int n_gamma = 0;

    const float span_z = 1.0f - 0.7f;
    const float span_s = 0.2f - 0.0f;
    const float span_g = 1.2f - 0.8f;

    for (int b = 0; b < BATCH; b++) {
        uint32_t kb0, kb1;
        tf2x32(0u, 42u, 0u, (uint32_t)b, kb0, kb1);

        uint32_t sk0[5], sk1[5];
        for (int j = 0; j < 5; j++) tf2x32(kb0, kb1, 0u, (uint32_t)j, sk0[j], sk1[j]);
        // order: kd, kz, ks, kn, kg
        float u[6];
        for (int i = 0; i < 6; i++)
            u[i] = bits_to_unit(xor_bits_host(sk0[0], sk1[0], (uint32_t)i));

        float z = 1.0f;
        if (u[0] < 0.15f) {
            float f = bits_to_unit(xor_bits_host(sk0[1], sk1[1], 0u));
            z = fmaxf(0.7f, f * span_z + 0.7f);
        }
        float stdv = 0.0f;
        if (u[4] < 0.1f) {
            float f = bits_to_unit(xor_bits_host(sk0[2], sk1[2], 0u));
            stdv = fmaxf(0.0f, f * span_s + 0.0f);
        }
        float gam = 1.0f;
        if (u[5] < 0.1f) {
            float f = bits_to_unit(xor_bits_host(sk0[4], sk1[4], 0u));
            gam = fmaxf(0.8f, f * span_g + 0.8f);
        }

        tmp[b].z    = z;
        tmp[b].stdv = stdv;
        tmp[b].b    = b;
        tmp[b].fh   = (u[1] < 0.5f) ? 1 : 0;
        tmp[b].fw   = (u[2] < 0.5f) ? 1 : 0;
        tmp[b].fd   = (u[3] < 0.5f) ? 1 : 0;
        tmp[b].kn0  = sk0[3];
        tmp[b].kn1  = sk1[3];
        tmp[b].need_stats = (gam != 1.0f) ? 1 : 0;
        if (gam != 1.0f) {
            G.sid[n_gamma] = b;
            G.g[n_gamma]   = gam;
            n_gamma++;
        }
    }

    // slots: gamma-needing samples FIRST [0, n_gamma), rest after
    AllParams P;
    int slot = 0;
    for (int b = 0; b < BATCH; b++) if (tmp[b].need_stats)  P.s[slot++] = tmp[b];
    for (int b = 0; b < BATCH; b++) if (!tmp[b].need_stats) P.s[slot++] = tmp[b];
    const int n_rest = BATCH - n_gamma;

    if (n_gamma == 0 || n_rest == 0) {
        AllParams Pa = P; Pa.slot_base = 0;
        dim3 grid(NV4 / 256, BATCH);
        aug_kernel<<<grid, 256>>>(img, lbl, out_img, out_lbl, Pa);
        if (n_gamma > 0) {
            dim3 ggrid(NV4 / (256 * G_UNROLL), n_gamma);
            G.total_blocks = (int)(ggrid.x * ggrid.y);
            gamma_kernel<<<ggrid, 256>>>(out_img, G);
        }
        return;
    }

    // fork-join: gamma samples + gamma kernel on the capture (legacy) stream,
    // remaining samples concurrently on a forked stream.
    cudaStream_t s2;
    cudaEvent_t evFork, evJoin;
    cudaStreamCreateWithFlags(&s2, cudaStreamNonBlocking);
    cudaEventCreateWithFlags(&evFork, cudaEventDisableTiming);
    cudaEventCreateWithFlags(&evJoin, cudaEventDisableTiming);

    cudaEventRecord(evFork, 0);
    cudaStreamWaitEvent(s2, evFork, 0);

    // stream2: the non-gamma samples
    {
        AllParams Pr = P; Pr.slot_base = n_gamma;
        dim3 grid(NV4 / 256, n_rest);
        aug_kernel<<<grid, 256, 0, s2>>>(img, lbl, out_img, out_lbl, Pr);
        cudaEventRecord(evJoin, s2);
    }

    // capture stream: gamma samples, then gamma (input hot in L2)
    {
        AllParams Pg = P; Pg.slot_base = 0;
        dim3 grid(NV4 / 256, n_gamma);
        aug_kernel<<<grid, 256>>>(img, lbl, out_img, out_lbl, Pg);
        dim3 ggrid(NV4 / (256 * G_UNROLL), n_gamma);
        G.total_blocks = (int)(ggrid.x * ggrid.y);
        gamma_kernel<<<ggrid, 256>>>(out_img, G);
    }

    cudaStreamWaitEvent(0, evJoin, 0);
}

// round 11
// speedup vs baseline: 1.1736x; 1.0434x over previous
#include <cuda_runtime.h>
#include <cstdint>
#include <cstring>
#include <math.h>

// ---------------------------------------------------------------------------
// DataAugmenter: zoom(linear/nearest) -> flips -> gaussian noise -> gamma.
// JAX threefry2x32, threefry_partitionable=True (validated R2).
// R11 = R10 (= R7 structure, 49.2us) + conditional cheap recompute:
//   if ALL gamma samples are flip-only (z==1, stdv==0), aug skips their
//   out_img store and gamma_cheap re-derives the augmented value by a pure
//   flip-copy load from img (bit-identical, no FLOPs), saving ~8-16MB DRAM.
//   Otherwise byte-for-byte R7/R10 behavior.
// ---------------------------------------------------------------------------

static const int BATCH = 8;
static const int NSIDE = 128;
static const int NVOX  = NSIDE * NSIDE * NSIDE;   // 2^21 per sample
static const int NV4   = NVOX / 4;                // float4 per sample

#define F32_INF __int_as_float(0x7F800000)

// ----------------------------- threefry2x32 --------------------------------
__host__ __device__ inline uint32_t rotl32(uint32_t v, int d) {
    return (v << d) | (v >> (32 - d));
}

__host__ __device__ inline void tf2x32(uint32_t k0, uint32_t k1,
                                       uint32_t c0, uint32_t c1,
                                       uint32_t& o0, uint32_t& o1) {
    uint32_t ks0 = k0, ks1 = k1, ks2 = 0x1BD11BDAu ^ k0 ^ k1;
    uint32_t x0 = c0 + ks0, x1 = c1 + ks1;
#define TFR(r) { x0 += x1; x1 = rotl32(x1, r); x1 ^= x0; }
    TFR(13) TFR(15) TFR(26) TFR(6)
    x0 += ks1; x1 += ks2 + 1u;
    TFR(17) TFR(29) TFR(16) TFR(24)
    x0 += ks2; x1 += ks0 + 2u;
    TFR(13) TFR(15) TFR(26) TFR(6)
    x0 += ks0; x1 += ks1 + 3u;
    TFR(17) TFR(29) TFR(16) TFR(24)
    x0 += ks1; x1 += ks2 + 4u;
    TFR(13) TFR(15) TFR(26) TFR(6)
    x0 += ks2; x1 += ks0 + 5u;
#undef TFR
    o0 = x0; o1 = x1;
}

__host__ __device__ inline float bits_to_unit(uint32_t bits) {
    uint32_t fb = (bits >> 9) | 0x3F800000u;
    float f;
#ifdef __CUDA_ARCH__
    f = __uint_as_float(fb);
#else
    memcpy(&f, &fb, 4);
#endif
    return f - 1.0f;
}

// XLA f32 ErfInv (Giles polynomial)
__device__ inline float erfinv_xla(float x) {
    float w = -log1pf(-x * x);
    float p;
    if (w < 5.0f) {
        w = w - 2.5f;
        p = 2.81022636e-08f;
        p = fmaf(p, w, 3.43273939e-07f);
        p = fmaf(p, w, -3.5233877e-06f);
        p = fmaf(p, w, -4.39150654e-06f);
        p = fmaf(p, w, 0.00021858087f);
        p = fmaf(p, w, -0.00125372503f);
        p = fmaf(p, w, -0.00417768164f);
        p = fmaf(p, w, 0.246640727f);
        p = fmaf(p, w, 1.50140941f);
    } else {
        w = sqrtf(w) - 3.0f;
        p = -0.000200214257f;
        p = fmaf(p, w, 0.000100950558f);
        p = fmaf(p, w, 0.00134934322f);
        p = fmaf(p, w, -0.00367342844f);
        p = fmaf(p, w, 0.00573950773f);
        p = fmaf(p, w, -0.0076224613f);
        p = fmaf(p, w, 0.00943887047f);
        p = fmaf(p, w, 1.00167406f);
        p = fmaf(p, w, 2.83297682f);
    }
    return p * x;
}

// ----------------------- ordered-uint min/max encoding ----------------------
__device__ inline unsigned encf(float f) {
    unsigned u = __float_as_uint(f);
    return (u & 0x80000000u) ? ~u : (u | 0x80000000u);
}
__device__ inline float decf(unsigned e) {
    unsigned u = (e & 0x80000000u) ? (e ^ 0x80000000u) : ~e;
    return __uint_as_float(u);
}

// Stats via atomicMax with identity 0 (zero-init compatible):
// max as encf(v), min as ~encf(v).
__device__ unsigned g_maxenc[BATCH];
__device__ unsigned g_negmin[BATCH];
__device__ unsigned g_done;

// ------------------------------- params ------------------------------------
struct SampleParams {
    float z;
    float stdv;
    int b;              // actual sample index
    int fh, fw, fd;
    int need_stats;
    int skip_img_store; // gamma sample whose value gamma_cheap re-derives
    uint32_t kn0, kn1;
};
struct AllParams { SampleParams s[BATCH]; int slot_base; };
struct GammaParams { int sid[BATCH]; float g[BATCH]; int total_blocks; };

// ------------------------------ main kernel --------------------------------
// One thread = 4 consecutive d-voxels (one float4).
// Handles slots [slot_base, slot_base + gridDim.y).
__global__ void __launch_bounds__(256)
aug_kernel(const float* __restrict__ img, const float* __restrict__ lbl,
           float* __restrict__ out_img, float* __restrict__ out_lbl,
           AllParams P) {
    const SampleParams sp = P.s[P.slot_base + blockIdx.y];
    const int b    = sp.b;
    const int idx4 = blockIdx.x * 256 + threadIdx.x;

    const int d4 = idx4 & 31;
    const int w  = (idx4 >> 5) & 127;
    const int h  = idx4 >> 12;
    const int hs = sp.fh ? 127 - h : h;
    const int ws = sp.fw ? 127 - w : w;

    const float* ib = img + (size_t)b * NVOX;
    const float* lb = lbl + (size_t)b * NVOX;

    float4 vi, vl;

    if (sp.z == 1.0f) {
        const int sd4 = sp.fd ? 31 - d4 : d4;
        const int s4  = (hs << 12) | (ws << 5) | sd4;
        float4 ti = reinterpret_cast<const float4*>(ib)[s4];
        float4 tl = reinterpret_cast<const float4*>(lb)[s4];
        if (sp.fd) {
            vi = make_float4(ti.w, ti.z, ti.y, ti.x);
            vl = make_float4(tl.w, tl.z, tl.y, tl.x);
        } else {
            vi = ti; vl = tl;
        }
    } else {
        const float z = sp.z;
        const float ch = (hs - 63.5f) / z + 63.5f;
        const float cw = (ws - 63.5f) / z + 63.5f;
        const int h0 = (int)floorf(ch), w0 = (int)floorf(cw);
        const float th = ch - (float)h0, tw = cw - (float)w0;
        float wh0 = (h0 >= 0 && h0 < NSIDE) ? (1.0f - th) : 0.0f;
        float wh1 = (h0 + 1 >= 0 && h0 + 1 < NSIDE) ? th : 0.0f;
        float ww0 = (w0 >= 0 && w0 < NSIDE) ? (1.0f - tw) : 0.0f;
        float ww1 = (w0 + 1 >= 0 && w0 + 1 < NSIDE) ? tw : 0.0f;
        int hc0 = min(max(h0, 0), 127), hc1 = min(max(h0 + 1, 0), 127);
        int wc0 = min(max(w0, 0), 127), wc1 = min(max(w0 + 1, 0), 127);
        const int rh = (int)rintf(ch), rw = (int)rintf(cw);
        const bool hv = (rh >= 0 && rh < NSIDE), wv = (rw >= 0 && rw < NSIDE);
        const int rhc = min(max(rh, 0), 127), rwc = min(max(rw, 0), 127);

        float ri[4], rl[4];
#pragma unroll
        for (int j = 0; j < 4; j++) {
            const int dd = 4 * d4 + j;
            const int ds = sp.fd ? 127 - dd : dd;
            const float cd = (ds - 63.5f) / z + 63.5f;
            const int d0 = (int)floorf(cd);
            const float td = cd - (float)d0;
            float wd0 = (d0 >= 0 && d0 < NSIDE) ? (1.0f - td) : 0.0f;
            float wd1 = (d0 + 1 >= 0 && d0 + 1 < NSIDE) ? td : 0.0f;
            int dc0 = min(max(d0, 0), 127), dc1 = min(max(d0 + 1, 0), 127);

            float h00 = wh0 * ib[(hc0 << 14) | (wc0 << 7) | dc0] + wh1 * ib[(hc1 << 14) | (wc0 << 7) | dc0];
            float h10 = wh0 * ib[(hc0 << 14) | (wc1 << 7) | dc0] + wh1 * ib[(hc1 << 14) | (wc1 << 7) | dc0];
            float h01 = wh0 * ib[(hc0 << 14) | (wc0 << 7) | dc1] + wh1 * ib[(hc1 << 14) | (wc0 << 7) | dc1];
            float h11 = wh0 * ib[(hc0 << 14) | (wc1 << 7) | dc1] + wh1 * ib[(hc1 << 14) | (wc1 << 7) | dc1];
            ri[j] = wd0 * (ww0 * h00 + ww1 * h10) + wd1 * (ww0 * h01 + ww1 * h11);

            const int rd = (int)rintf(cd);
            const bool valid = hv && wv && (rd >= 0 && rd < NSIDE);
            const int rdc = min(max(rd, 0), 127);
            rl[j] = valid ? lb[(rhc << 14) | (rwc << 7) | rdc] : 0.0f;
        }
        vi = make_float4(ri[0], ri[1], ri[2], ri[3]);
        vl = make_float4(rl[0], rl[1], rl[2], rl[3]);
    }

    if (sp.stdv > 0.0f) {
        float* pv = &vi.x;
#pragma unroll
        for (int j = 0; j < 4; j++) {
            uint32_t o0, o1;
            tf2x32(sp.kn0, sp.kn1, 0u, (uint32_t)(4 * idx4 + j), o0, o1);
            float f = bits_to_unit(o0 ^ o1);
            const float lo = -0.99999994f;           // nextafter(-1, 0)
            float u = fmaxf(lo, f * 2.0f + lo);
            pv[j] += sp.stdv * (1.41421356f * erfinv_xla(u));
        }
    }

    if (!sp.skip_img_store)
        reinterpret_cast<float4*>(out_img)[(size_t)b * NV4 + idx4] = vi;
    // labels are never re-read -> streaming store
    __stcs(reinterpret_cast<float4*>(out_lbl) + (size_t)b * NV4 + idx4, vl);

    if (sp.need_stats) {
        float vmin = fminf(fminf(vi.x, vi.y), fminf(vi.z, vi.w));
        float vmax = fmaxf(fmaxf(vi.x, vi.y), fmaxf(vi.z, vi.w));
#pragma unroll
        for (int o = 16; o > 0; o >>= 1) {
            vmin = fminf(vmin, __shfl_down_sync(0xFFFFFFFFu, vmin, o));
            vmax = fmaxf(vmax, __shfl_down_sync(0xFFFFFFFFu, vmax, o));
        }
        __shared__ float smin[8], smax[8];
        int lane = threadIdx.x & 31, wid = threadIdx.x >> 5;
        if (lane == 0) { smin[wid] = vmin; smax[wid] = vmax; }
        __syncthreads();
        if (wid == 0) {
            vmin = (lane < 8) ? smin[lane] : F32_INF;
            vmax = (lane < 8) ? smax[lane] : -F32_INF;
#pragma unroll
            for (int o = 4; o > 0; o >>= 1) {
                vmin = fminf(vmin, __shfl_down_sync(0xFFFFFFFFu, vmin, o));
                vmax = fmaxf(vmax, __shfl_down_sync(0xFFFFFFFFu, vmax, o));
            }
            if (lane == 0) {
                atomicMax(&g_maxenc[b], encf(vmax));
                atomicMax(&g_negmin[b], ~encf(vmin));
            }
        }
    }
}

// ---------------------- gamma kernel (normal, R7 path) ----------------------
// 2 float4/thread. Reads out_img, gamma, writes back.
static const int G_UNROLL = 2;
__global__ void __launch_bounds__(256)
gamma_kernel(float* __restrict__ out_img, GammaParams G) {
    const int b     = G.sid[blockIdx.y];
    const float gam = G.g[blockIdx.y];
    const int base  = blockIdx.x * (256 * G_UNROLL) + threadIdx.x;

    const float mn  = decf(~g_negmin[b]);
    const float mx  = decf(g_maxenc[b]);
    const float rng = mx - mn;
    const float inv = 1.0f / (rng + 1e-7f);

    float4* p = reinterpret_cast<float4*>(out_img) + (size_t)b * NV4;

    float4 v[G_UNROLL];
#pragma unroll
    for (int k = 0; k < G_UNROLL; k++)
        v[k] = p[base + k * 256];

#pragma unroll
    for (int k = 0; k < G_UNROLL; k++) {
        float* pv = &v[k].x;
#pragma unroll
        for (int j = 0; j < 4; j++) {
            float xn = fminf(fmaxf((pv[j] - mn) * inv, 1e-6f), 1.0f);
            pv[j] = __powf(xn, gam) * rng + mn;
        }
    }

#pragma unroll
    for (int k = 0; k < G_UNROLL; k++)
        __stcs(p + base + k * 256, v[k]);

    __syncthreads();
    if (threadIdx.x == 0) {
        __threadfence();
        unsigned old = atomicAdd(&g_done, 1u);
        if (old == (unsigned)(G.total_blocks - 1)) {
            for (int i = 0; i < BATCH; i++) { g_maxenc[i] = 0u; g_negmin[i] = 0u; }
            __threadfence();
            g_done = 0u;
        }
    }
}

// -------------------- gamma kernel (cheap flip-only path) -------------------
// Gamma samples guaranteed z==1 && stdv==0: augmented value == flip-copy of
// img (bit-identical to aug's vi). Reads img (L2-warm), applies gamma,
// writes out_img once. Gamma samples occupy slots [0, gridDim.y).
__global__ void __launch_bounds__(256)
gamma_cheap_kernel(const float* __restrict__ img, float* __restrict__ out_img,
                   AllParams P, GammaParams G) {
    const SampleParams sp = P.s[blockIdx.y];
    const int b     = sp.b;
    const float gam = G.g[blockIdx.y];
    const int base  = blockIdx.x * (256 * G_UNROLL) + threadIdx.x;

    const float mn  = decf(~g_negmin[b]);
    const float mx  = decf(g_maxenc[b]);
    const float rng = mx - mn;
    const float inv = 1.0f / (rng + 1e-7f);

    const float4* ib = reinterpret_cast<const float4*>(img + (size_t)b * NVOX);
    float4* p = reinterpret_cast<float4*>(out_img) + (size_t)b * NV4;

    float4 v[G_UNROLL];
#pragma unroll
    for (int k = 0; k < G_UNROLL; k++) {
        const int idx4 = base + k * 256;
        const int d4 = idx4 & 31;
        const int w  = (idx4 >> 5) & 127;
        const int h  = idx4 >> 12;
        const int hs = sp.fh ? 127 - h : h;
        const int ws = sp.fw ? 127 - w : w;
        const int sd4 = sp.fd ? 31 - d4 : d4;
        float4 ti = ib[(hs << 12) | (ws << 5) | sd4];
        v[k] = sp.fd ? make_float4(ti.w, ti.z, ti.y, ti.x) : ti;
    }

#pragma unroll
    for (int k = 0; k < G_UNROLL; k++) {
        float* pv = &v[k].x;
#pragma unroll
        for (int j = 0; j < 4; j++) {
            float xn = fminf(fmaxf((pv[j] - mn) * inv, 1e-6f), 1.0f);
            pv[j] = __powf(xn, gam) * rng + mn;
        }
    }

#pragma unroll
    for (int k = 0; k < G_UNROLL; k++)
        __stcs(p + base + k * 256, v[k]);

    __syncthreads();
    if (threadIdx.x == 0) {
        __threadfence();
        unsigned old = atomicAdd(&g_done, 1u);
        if (old == (unsigned)(G.total_blocks - 1)) {
            for (int i = 0; i < BATCH; i++) { g_maxenc[i] = 0u; g_negmin[i] = 0u; }
            __threadfence();
            g_done = 0u;
        }
    }
}

// ------------------------------- host side ----------------------------------
static inline uint32_t xor_bits_host(uint32_t k0, uint32_t k1, uint32_t c1) {
    uint32_t o0, o1;
    tf2x32(k0, k1, 0u, c1, o0, o1);
    return o0 ^ o1;
}

extern "C" void kernel_launch(void* const* d_in, const int* in_sizes, int n_in,
                              void* d_out, int out_size) {
    const float* img = (const float*)d_in[0];
    const float* lbl = (const float*)d_in[1];
    float* out_img = (float*)d_out;
    float* out_lbl = (float*)d_out + (size_t)BATCH * NVOX;

    SampleParams tmp[BATCH];
    GammaParams G;
    int n_gamma = 0;

    const float span_z = 1.0f - 0.7f;
    const float span_s = 0.2f - 0.0f;
    const float span_g = 1.2f - 0.8f;

    for (int b = 0; b < BATCH; b++) {
        uint32_t kb0, kb1;
        tf2x32(0u, 42u, 0u, (uint32_t)b, kb0, kb1);

        uint32_t sk0[5], sk1[5];
        for (int j = 0; j < 5; j++) tf2x32(kb0, kb1, 0u, (uint32_t)j, sk0[j], sk1[j]);
        // order: kd, kz, ks, kn, kg
        float u[6];
        for (int i = 0; i < 6; i++)
            u[i] = bits_to_unit(xor_bits_host(sk0[0], sk1[0], (uint32_t)i));

        float z = 1.0f;
        if (u[0] < 0.15f) {
            float f = bits_to_unit(xor_bits_host(sk0[1], sk1[1], 0u));
            z = fmaxf(0.7f, f * span_z + 0.7f);
        }
        float stdv = 0.0f;
        if (u[4] < 0.1f) {
            float f = bits_to_unit(xor_bits_host(sk0[2], sk1[2], 0u));
            stdv = fmaxf(0.0f, f * span_s + 0.0f);
        }
        float gam = 1.0f;
        if (u[5] < 0.1f) {
            float f = bits_to_unit(xor_bits_host(sk0[4], sk1[4], 0u));
            gam = fmaxf(0.8f, f * span_g + 0.8f);
        }

        tmp[b].z    = z;
        tmp[b].stdv = stdv;
        tmp[b].b    = b;
        tmp[b].fh   = (u[1] < 0.5f) ? 1 : 0;
        tmp[b].fw   = (u[2] < 0.5f) ? 1 : 0;
        tmp[b].fd   = (u[3] < 0.5f) ? 1 : 0;
        tmp[b].kn0  = sk0[3];
        tmp[b].kn1  = sk1[3];
        tmp[b].need_stats = (gam != 1.0f) ? 1 : 0;
        tmp[b].skip_img_store = 0;
        if (gam != 1.0f) {
            G.sid[n_gamma] = b;
            G.g[n_gamma]   = gam;
            n_gamma++;
        }
    }

    // cheap recompute only if EVERY gamma sample is a pure flip-copy
    bool all_cheap = (n_gamma > 0);
    for (int b = 0; b < BATCH; b++)
        if (tmp[b].need_stats && !(tmp[b].z == 1.0f && tmp[b].stdv == 0.0f))
            all_cheap = false;
    if (all_cheap)
        for (int b = 0; b < BATCH; b++)
            if (tmp[b].need_stats) tmp[b].skip_img_store = 1;

    // slots: gamma-needing samples FIRST [0, n_gamma), rest after
    AllParams P;
    int slot = 0;
    for (int b = 0; b < BATCH; b++) if (tmp[b].need_stats)  P.s[slot++] = tmp[b];
    for (int b = 0; b < BATCH; b++) if (!tmp[b].need_stats) P.s[slot++] = tmp[b];
    const int n_rest = BATCH - n_gamma;

    if (n_gamma == 0 || n_rest == 0) {
        AllParams Pa = P; Pa.slot_base = 0;
        dim3 grid(NV4 / 256, BATCH);
        aug_kernel<<<grid, 256>>>(img, lbl, out_img, out_lbl, Pa);
        if (n_gamma > 0) {
            dim3 ggrid(NV4 / (256 * G_UNROLL), n_gamma);
            G.total_blocks = (int)(ggrid.x * ggrid.y);
            if (all_cheap)
                gamma_cheap_kernel<<<ggrid, 256>>>(img, out_img, Pa, G);
            else
                gamma_kernel<<<ggrid, 256>>>(out_img, G);
        }
        return;
    }

    // fork-join: gamma samples + gamma kernel on the capture (legacy) stream,
    // remaining samples concurrently on a forked stream.
    cudaStream_t s2;
    cudaEvent_t evFork, evJoin;
    cudaStreamCreateWithFlags(&s2, cudaStreamNonBlocking);
    cudaEventCreateWithFlags(&evFork, cudaEventDisableTiming);
    cudaEventCreateWithFlags(&evJoin, cudaEventDisableTiming);

    cudaEventRecord(evFork, 0);
    cudaStreamWaitEvent(s2, evFork, 0);

    // stream2: the non-gamma samples
    {
        AllParams Pr = P; Pr.slot_base = n_gamma;
        dim3 grid(NV4 / 256, n_rest);
        aug_kernel<<<grid, 256, 0, s2>>>(img, lbl, out_img, out_lbl, Pr);
        cudaEventRecord(evJoin, s2);
    }

    // capture stream: gamma samples' aug, then gamma
    {
        AllParams Pg = P; Pg.slot_base = 0;
        dim3 grid(NV4 / 256, n_gamma);
        aug_kernel<<<grid, 256>>>(img, lbl, out_img, out_lbl, Pg);
        dim3 ggrid(NV4 / (256 * G_UNROLL), n_gamma);
        G.total_blocks = (int)(ggrid.x * ggrid.y);
        if (all_cheap)
            gamma_cheap_kernel<<<ggrid, 256>>>(img, out_img, Pg, G);
        else
            gamma_kernel<<<ggrid, 256>>>(out_img, G);
    }

    cudaStreamWaitEvent(0, evJoin, 0);
}